// round 14
// baseline (speedup 1.0000x reference)
#include <cuda_runtime.h>
#include <cuda_fp16.h>
#include <cstdint>

// ---------------------------------------------------------------------------
// EfficientAttention: R11 structure (256 thr, 8192 blocks, 64-token tiles,
// f16 mma.sync m16n8k16 + ldmatrix, f16 Q scratch) with:
//  - vectorized ctx reduction (128 combos x 2 row-halves, float4 V loads)
//  - __launch_bounds__ occupancy hints
//  - 32-block setup kernel
// N=2, D=64, H=W=64, C=64, HEADS=8. token = c*4096 + h*64 + w.
// f16 MMA tiles: row = 64 halves = 8 chunks of 16B; chunk c of row r at byte
// r*128 + ((c ^ (r&7))<<4)  (conflict-free for ldmatrix).
// ---------------------------------------------------------------------------

typedef uint32_t u32;

#define T_TOK 262144
#define PLANE 262144

__device__ __half g_Qh[(size_t)2 * T_TOK * 64];  // 64 MiB Q scratch (f16)
__device__ __half g_WTh[4 * 4096];               // WqT,WkT,WvT,WrT f16 [e][d]
__device__ float  g_ctxnum[2 * 512];
__device__ float  g_den[2 * 64];

__device__ __forceinline__ float lrelu(float y) { return y >= 0.f ? y : 0.2f * y; }
static __device__ __forceinline__ u32 s2u(const void* p) {
    u32 a; asm("{ .reg .u64 t; cvta.to.shared.u64 t, %1; cvt.u32.u64 %0, t; }"
               : "=r"(a) : "l"(p)); return a;
}
__device__ __forceinline__ u32 choff(int r, int c) {
    return (u32)(r * 128 + ((c ^ (r & 7)) << 4));
}
// 4B-granular swizzled offset for the f16 Q stash (row = token, ch = channel)
__device__ __forceinline__ u32 qoff(int r, int ch) {
    return (u32)(r * 128 + ((2 * ch) ^ ((r & 7) << 4)));
}
__device__ __forceinline__ void ldmA(u32 addr, u32 r[4]) {
    asm volatile("ldmatrix.sync.aligned.m8n8.x4.shared.b16 {%0,%1,%2,%3}, [%4];"
                 : "=r"(r[0]), "=r"(r[1]), "=r"(r[2]), "=r"(r[3]) : "r"(addr));
}
__device__ __forceinline__ void ldmB(u32 addr, u32 r[2]) {
    asm volatile("ldmatrix.sync.aligned.m8n8.x2.shared.b16 {%0,%1}, [%2];"
                 : "=r"(r[0]), "=r"(r[1]) : "r"(addr));
}
__device__ __forceinline__ void mma16(float c[4], const u32 a[4], const u32 b[2]) {
    asm volatile(
        "mma.sync.aligned.m16n8k16.row.col.f32.f16.f16.f32 "
        "{%0,%1,%2,%3}, {%4,%5,%6,%7}, {%8,%9}, {%0,%1,%2,%3};"
        : "+f"(c[0]), "+f"(c[1]), "+f"(c[2]), "+f"(c[3])
        : "r"(a[0]), "r"(a[1]), "r"(a[2]), "r"(a[3]), "r"(b[0]), "r"(b[1]));
}

// 32 blocks: block b transposes 8 rows (e = (b&7)*8..+8) of matrix b>>3.
__global__ void setup_kernel(const float* __restrict__ Wq, const float* __restrict__ Wk,
                             const float* __restrict__ Wv, const float* __restrict__ Wr) {
    const int t = threadIdx.x, b = blockIdx.x;
    const int mat = b >> 3, slice = b & 7;
    const float* W = (mat == 0) ? Wq : (mat == 1) ? Wk : (mat == 2) ? Wv : Wr;
    __half* dst = g_WTh + mat * 4096;
    const int e = slice * 8 + (t >> 5);
    const int d0 = (t & 31) * 2;
    __half2 p = __floats2half2_rn(W[d0 * 64 + e], W[(d0 + 1) * 64 + e]);
    *(__half2*)(dst + e * 64 + d0) = p;
    if (b == 0) {
        for (int i = t; i < 1024; i += 256) g_ctxnum[i] = 0.f;
        if (t < 128) g_den[t] = 0.f;
    }
}

// -------- passA smem byte map (53760 B static) --------
// Stage phase:   XS f16 [c][d] @0 (8192) ; WS f16 3x @8192 (24576) ; SB @52224
// Epilogue phase: QSh f16 @0 (8192), EK f32 @17408, VS f32 @34816
// ctx combine (after g_Qh write): parts f4 @0 (2048), dparts @2048 (512)
__global__ void __launch_bounds__(256, 3) passA_kernel(
    const float* __restrict__ x,
    const float* __restrict__ sk, const float* __restrict__ bk,
    const float* __restrict__ sq, const float* __restrict__ bq,
    const float* __restrict__ sv, const float* __restrict__ bv)
{
    static __shared__ __align__(16) char SM[53760];
    const u32 sb = s2u(SM);
    float* EK = (float*)(SM + 17408);
    float* VS = (float*)(SM + 34816);
    float* SB = (float*)(SM + 52224);
    const int t = threadIdx.x, lane = t & 31, w = t >> 5;
    const int grp = lane >> 2, q = lane & 3, l7 = lane & 7;
    const int b = blockIdx.x, n = b >> 12, hw = b & 4095;
    const size_t xb = (size_t)n * (64ull * PLANE) + (size_t)hw * 64;

    // ---- stage XS f16: row = token c (t&63), 2 d-chunks per thread ----
    {
        const int row = t & 63, u0 = (t >> 6) * 2;
#pragma unroll
        for (int uu = 0; uu < 2; uu++) {
            int u = u0 + uu;
            float f[8];
#pragma unroll
            for (int j = 0; j < 8; j++)
                f[j] = x[xb + (size_t)(8 * u + j) * PLANE + row];
            __half2 p[4];
#pragma unroll
            for (int j = 0; j < 4; j++) p[j] = __floats2half2_rn(f[2 * j], f[2 * j + 1]);
            *(uint4*)(SM + choff(row, u)) = *(uint4*)p;
        }
    }
    // ---- stage WqT/WkT/WvT f16 ----
    {
        const uint4* g4 = (const uint4*)g_WTh;
#pragma unroll
        for (int i = 0; i < 6; i++) {
            int idx = i * 256 + t;                 // 0..1535
            int mat = idx >> 9, rem = idx & 511;
            uint4 v = g4[idx];
            *(uint4*)(SM + 8192 + mat * 8192 + choff(rem >> 3, rem & 7)) = v;
        }
    }
    if (t < 64) {
        SB[t]       = sq[t]; SB[64  + t] = bq[t];
        SB[128 + t] = sk[t]; SB[192 + t] = bk[t];
        SB[256 + t] = sv[t]; SB[320 + t] = bv[t];
    }
    __syncthreads();

    // ---- GEMMs: warp tile = 16 rows (mtile) x 32 cols (nhalf); shared A frags ----
    const int mtile = (w & 3) * 16, nhalf = (w >> 2) * 32;
    const int arow0 = mtile + l7 + (((lane >> 3) & 1) << 3);
    const int acs = lane >> 4, bcs = (lane >> 3) & 1;
    float accQ[4][4], accK[4][4], accV[4][4];
#pragma unroll
    for (int nt = 0; nt < 4; nt++)
#pragma unroll
        for (int k = 0; k < 4; k++) { accQ[nt][k] = 0.f; accK[nt][k] = 0.f; accV[nt][k] = 0.f; }
#pragma unroll
    for (int kt = 0; kt < 4; kt++) {
        u32 a4[4];
        ldmA(sb + choff(arow0, 2 * kt + acs), a4);
#pragma unroll
        for (int nt = 0; nt < 4; nt++) {
            const u32 bo = choff(nhalf + nt * 8 + l7, 2 * kt + bcs);
            u32 b0[2], b1[2], b2[2];
            ldmB(sb + 8192 + bo, b0);
            ldmB(sb + 16384 + bo, b1);
            ldmB(sb + 24576 + bo, b2);
            mma16(accQ[nt], a4, b0);
            mma16(accK[nt], a4, b1);
            mma16(accV[nt], a4, b2);
        }
    }
    __syncthreads();      // all MMAs done; stage regions may be overwritten

    // ---- Q: quad-shuffle softmax -> QSh f16 ; K: exp -> EK ; V -> VS ----
#pragma unroll
    for (int rr = 0; rr < 2; rr++) {
        const int row = mtile + rr * 8 + grp;
#pragma unroll
        for (int nt = 0; nt < 4; nt++) {
            const int ch = nhalf + nt * 8 + 2 * q;
            {
                float y0 = lrelu(accQ[nt][rr * 2 + 0] * SB[ch]     + SB[64 + ch]);
                float y1 = lrelu(accQ[nt][rr * 2 + 1] * SB[ch + 1] + SB[64 + ch + 1]);
                float m = fmaxf(y0, y1);
                m = fmaxf(m, __shfl_xor_sync(0xffffffffu, m, 1));
                m = fmaxf(m, __shfl_xor_sync(0xffffffffu, m, 2));
                float e0 = __expf(y0 - m), e1 = __expf(y1 - m);
                float s = e0 + e1;
                s += __shfl_xor_sync(0xffffffffu, s, 1);
                s += __shfl_xor_sync(0xffffffffu, s, 2);
                float inv = 1.f / s;
                *(__half2*)(SM + qoff(row, ch)) = __floats2half2_rn(e0 * inv, e1 * inv);
            }
            {
                float e0 = __expf(lrelu(accK[nt][rr * 2 + 0] * SB[128 + ch]     + SB[192 + ch]));
                float e1 = __expf(lrelu(accK[nt][rr * 2 + 1] * SB[128 + ch + 1] + SB[192 + ch + 1]));
                *(float2*)(EK + row * 68 + ch) = make_float2(e0, e1);
            }
            {
                float v0 = lrelu(accV[nt][rr * 2 + 0] * SB[256 + ch]     + SB[320 + ch]);
                float v1 = lrelu(accV[nt][rr * 2 + 1] * SB[256 + ch + 1] + SB[320 + ch + 1]);
                *(float2*)(VS + row * 68 + ch) = make_float2(v0, v1);
            }
        }
    }
    __syncthreads();

    // ---- g_Qh write: coalesced 128B f16 rows ----
    {
        const size_t qbase = ((size_t)n * T_TOK + hw) * 64;   // halves
#pragma unroll
        for (int i = 0; i < 2; i++) {
            int idx = t + i * 256;                 // 0..511
            int row = idx >> 3, u = idx & 7;
            uint4 v = *(const uint4*)(SM + row * 128 + ((16 * u) ^ ((row & 7) << 4)));
            *(uint4*)(g_Qh + qbase + (size_t)row * PLANE + 8 * u) = v;
        }
    }
    __syncthreads();      // QSh region retired; reuse [0,2560) for ctx partials

    // ---- ctx num/den, vectorized: thread = (a,k,vh) x row-half ----
    {
        float4* parts  = (float4*)SM;             // [128]
        float*  dparts = (float*)(SM + 2048);     // [128]
        const int combo = t & 127, rh = t >> 7;
        const int vh = combo & 1, k2 = (combo >> 1) & 7, a2 = combo >> 4;
        const float* ekp = EK + (rh * 32) * 68 + a2 * 8 + k2;
        const float* vvp = VS + (rh * 32) * 68 + a2 * 8 + 4 * vh;
        float4 cacc = make_float4(0.f, 0.f, 0.f, 0.f);
        float dsum = 0.f;
#pragma unroll 8
        for (int i = 0; i < 32; i++) {
            float ek = ekp[i * 68];
            float4 v4 = *(const float4*)(vvp + i * 68);
            cacc.x += ek * v4.x; cacc.y += ek * v4.y;
            cacc.z += ek * v4.z; cacc.w += ek * v4.w;
            dsum += ek;
        }
        if (rh == 1) { parts[combo] = cacc; dparts[combo] = dsum; }
        __syncthreads();
        if (t < 128) {
            float4 p = parts[t];
            float* dst = g_ctxnum + n * 512 + a2 * 64 + k2 * 8 + 4 * vh;
            atomicAdd(dst + 0, cacc.x + p.x);
            atomicAdd(dst + 1, cacc.y + p.y);
            atomicAdd(dst + 2, cacc.z + p.z);
            atomicAdd(dst + 3, cacc.w + p.w);
            if (vh == 0) atomicAdd(g_den + n * 64 + a2 * 8 + k2, dsum + dparts[t]);
        }
    }
}

// -------- passC smem byte map (36352 B static) --------
// Qs f32[64][68] @0 (17408) ; WrS f16 @17408 (8192) ; Ag f16 @25600 (8192)
// ctx @33792 (2048) ; SBc @35840 (512)
__global__ void __launch_bounds__(256, 4) passC_kernel(
    const float* __restrict__ x,
    const float* __restrict__ sr, const float* __restrict__ br,
    float* __restrict__ out)
{
    static __shared__ __align__(16) char SM[36352];
    const u32 sb = s2u(SM);
    float* Qs   = (float*)SM;
    float* ctxs = (float*)(SM + 33792);
    float* SBc  = (float*)(SM + 35840);
    const int t = threadIdx.x, lane = t & 31, w = t >> 5;
    const int grp = lane >> 2, q = lane & 3, l7 = lane & 7;
    const int b = blockIdx.x, n = b >> 12, hw = b & 4095;
    const int h = hw >> 6, ww = hw & 63;
    const size_t qn = (size_t)n * T_TOK * 64;   // halves

    {   // stage WrS
        const uint4* g4 = (const uint4*)g_WTh + 3 * 512;
#pragma unroll
        for (int i = 0; i < 2; i++) {
            int idx = i * 256 + t;                 // 0..511
            uint4 v = g4[idx];
            *(uint4*)(SM + 17408 + choff(idx >> 3, idx & 7)) = v;
        }
    }
#pragma unroll
    for (int g = t; g < 512; g += 256)
        ctxs[g] = g_ctxnum[n * 512 + g] / g_den[n * 64 + (g >> 3)];
    if (t < 64) { SBc[t] = sr[t]; SBc[64 + t] = br[t]; }
    {   // Q gather: f16 global rows -> f32 Qs[rv][68]
#pragma unroll
        for (int i = 0; i < 2; i++) {
            int idx = t + i * 256;                 // 0..511
            int rv = idx >> 3, u = idx & 7;
            int r = rv >> 3, v = rv & 7;
            size_t R = (size_t)r * 32768 + (size_t)h * 512 + ww * 8 + v;
            uint4 q4 = *(const uint4*)(g_Qh + qn + R * 64 + 8 * u);
            const __half2* hp = (const __half2*)&q4;
            float* dst = Qs + rv * 68 + 8 * u;
            float2 f0 = __half22float2(hp[0]), f1 = __half22float2(hp[1]);
            float2 f2 = __half22float2(hp[2]), f3 = __half22float2(hp[3]);
            *(float4*)dst       = make_float4(f0.x, f0.y, f1.x, f1.y);
            *(float4*)(dst + 4) = make_float4(f2.x, f2.y, f3.x, f3.y);
        }
    }
    __syncthreads();

    // ---- agg (verified R1 math) -> Ag f16 A-tile ----
    {
        const int cg = (t & 15) << 2;
        const int eg = (t >> 4) << 2;
        const int a  = eg >> 3;
#pragma unroll
        for (int i = 0; i < 4; i++) {
            int c = cg + i;
            int k = c >> 3, rr = (c & 7) << 3;
            float4 cx0 = *(const float4*)(ctxs + (a * 8 + k) * 8);
            float4 cx1 = *(const float4*)(ctxs + (a * 8 + k) * 8 + 4);
            float av[4];
#pragma unroll
            for (int j = 0; j < 4; j++) {
                int v = (eg + j) & 7;
                const float* qp = Qs + (rr + v) * 68 + a * 8;
                float4 q0 = *(const float4*)qp;
                float4 q1 = *(const float4*)(qp + 4);
                av[j] = cx0.x * q0.x + cx0.y * q0.y + cx0.z * q0.z + cx0.w * q0.w
                      + cx1.x * q1.x + cx1.y * q1.y + cx1.z * q1.z + cx1.w * q1.w;
            }
            __half2 p0 = __floats2half2_rn(av[0], av[1]);
            __half2 p1 = __floats2half2_rn(av[2], av[3]);
            uint2 pk; pk.x = *(u32*)&p0; pk.y = *(u32*)&p1;
            *(uint2*)(SM + 25600 + choff(c, eg >> 3) + (eg & 7) * 2) = pk;
        }
    }
    __syncthreads();

    // ---- rep = agg @ Wr via MMA ----
    const int mtile = (w & 3) * 16, nhalf = (w >> 2) * 32;
    const int arow0 = mtile + l7 + (((lane >> 3) & 1) << 3);
    const int acs = lane >> 4, bcs = (lane >> 3) & 1;
    float accR[4][4];
#pragma unroll
    for (int nt = 0; nt < 4; nt++)
#pragma unroll
        for (int k = 0; k < 4; k++) accR[nt][k] = 0.f;
#pragma unroll
    for (int kt = 0; kt < 4; kt++) {
        u32 a4[4];
        ldmA(sb + 25600 + choff(arow0, 2 * kt + acs), a4);
#pragma unroll
        for (int nt = 0; nt < 4; nt++) {
            u32 b2[2];
            ldmB(sb + 17408 + choff(nhalf + nt * 8 + l7, 2 * kt + bcs), b2);
            mma16(accR[nt], a4, b2);
        }
    }

    // ---- epilogue: scale/bias/lrelu + residual ----
    {
        const size_t ob = (size_t)n * (64ull * PLANE) + (size_t)hw * 64;
#pragma unroll
        for (int rr = 0; rr < 2; rr++) {
            const int c = mtile + rr * 8 + grp;
#pragma unroll
            for (int nt = 0; nt < 4; nt++) {
#pragma unroll
                for (int j = 0; j < 2; j++) {
                    const int d = nhalf + nt * 8 + 2 * q + j;
                    float yv = lrelu(accR[nt][rr * 2 + j] * SBc[d] + SBc[64 + d]);
                    const size_t off = ob + (size_t)d * PLANE + c;
                    out[off] = yv + x[off];
                }
            }
        }
    }
}

extern "C" void kernel_launch(void* const* d_in, const int* in_sizes, int n_in,
                              void* d_out, int out_size) {
    const float* x  = (const float*)d_in[0];
    const float* Wk = (const float*)d_in[1];
    const float* sk = (const float*)d_in[2];
    const float* bk = (const float*)d_in[3];
    const float* Wq = (const float*)d_in[4];
    const float* sq = (const float*)d_in[5];
    const float* bq = (const float*)d_in[6];
    const float* Wv = (const float*)d_in[7];
    const float* sv = (const float*)d_in[8];
    const float* bv = (const float*)d_in[9];
    const float* Wr = (const float*)d_in[10];
    const float* sr = (const float*)d_in[11];
    const float* br = (const float*)d_in[12];
    float* out = (float*)d_out;

    setup_kernel<<<32, 256>>>(Wq, Wk, Wv, Wr);
    passA_kernel<<<8192, 256>>>(x, sk, bk, sq, bq, sv, bv);
    passC_kernel<<<8192, 256>>>(x, sr, br, out);
}

// round 15
// speedup vs baseline: 1.4993x; 1.4993x over previous
#include <cuda_runtime.h>
#include <cuda_fp16.h>
#include <cstdint>

// ---------------------------------------------------------------------------
// EfficientAttention: R11 structure exactly (256 thr, 8192 blocks, 64-token
// tiles, f16 mma.sync m16n8k16 + ldmatrix, f16 Q scratch, R1-verified
// ctx/agg math), plus the 32-block setup kernel (measured win).
// NO __launch_bounds__ minBlocks hints (R14 regression: forced reg caps ->
// spills in both passes).
// N=2, D=64, H=W=64, C=64, HEADS=8. token = c*4096 + h*64 + w.
// f16 MMA tiles: row = 64 halves = 8 chunks of 16B; chunk c of row r at byte
// r*128 + ((c ^ (r&7))<<4)  (conflict-free for ldmatrix).
// ---------------------------------------------------------------------------

typedef uint32_t u32;

#define T_TOK 262144
#define PLANE 262144

__device__ __half g_Qh[(size_t)2 * T_TOK * 64];  // 64 MiB Q scratch (f16)
__device__ __half g_WTh[4 * 4096];               // WqT,WkT,WvT,WrT f16 [e][d]
__device__ float  g_ctxnum[2 * 512];
__device__ float  g_den[2 * 64];

__device__ __forceinline__ float lrelu(float y) { return y >= 0.f ? y : 0.2f * y; }
static __device__ __forceinline__ u32 s2u(const void* p) {
    u32 a; asm("{ .reg .u64 t; cvta.to.shared.u64 t, %1; cvt.u32.u64 %0, t; }"
               : "=r"(a) : "l"(p)); return a;
}
__device__ __forceinline__ u32 choff(int r, int c) {
    return (u32)(r * 128 + ((c ^ (r & 7)) << 4));
}
// 4B-granular swizzled offset for the f16 Q stash (row = token, ch = channel)
__device__ __forceinline__ u32 qoff(int r, int ch) {
    return (u32)(r * 128 + ((2 * ch) ^ ((r & 7) << 4)));
}
__device__ __forceinline__ void ldmA(u32 addr, u32 r[4]) {
    asm volatile("ldmatrix.sync.aligned.m8n8.x4.shared.b16 {%0,%1,%2,%3}, [%4];"
                 : "=r"(r[0]), "=r"(r[1]), "=r"(r[2]), "=r"(r[3]) : "r"(addr));
}
__device__ __forceinline__ void ldmB(u32 addr, u32 r[2]) {
    asm volatile("ldmatrix.sync.aligned.m8n8.x2.shared.b16 {%0,%1}, [%2];"
                 : "=r"(r[0]), "=r"(r[1]) : "r"(addr));
}
__device__ __forceinline__ void mma16(float c[4], const u32 a[4], const u32 b[2]) {
    asm volatile(
        "mma.sync.aligned.m16n8k16.row.col.f32.f16.f16.f32 "
        "{%0,%1,%2,%3}, {%4,%5,%6,%7}, {%8,%9}, {%0,%1,%2,%3};"
        : "+f"(c[0]), "+f"(c[1]), "+f"(c[2]), "+f"(c[3])
        : "r"(a[0]), "r"(a[1]), "r"(a[2]), "r"(a[3]), "r"(b[0]), "r"(b[1]));
}

// 32 blocks: block b transposes 8 rows (e = (b&7)*8..+8) of matrix b>>3.
__global__ void setup_kernel(const float* __restrict__ Wq, const float* __restrict__ Wk,
                             const float* __restrict__ Wv, const float* __restrict__ Wr) {
    const int t = threadIdx.x, b = blockIdx.x;
    const int mat = b >> 3, slice = b & 7;
    const float* W = (mat == 0) ? Wq : (mat == 1) ? Wk : (mat == 2) ? Wv : Wr;
    __half* dst = g_WTh + mat * 4096;
    const int e = slice * 8 + (t >> 5);
    const int d0 = (t & 31) * 2;
    __half2 p = __floats2half2_rn(W[d0 * 64 + e], W[(d0 + 1) * 64 + e]);
    *(__half2*)(dst + e * 64 + d0) = p;
    if (b == 0) {
        for (int i = t; i < 1024; i += 256) g_ctxnum[i] = 0.f;
        if (t < 128) g_den[t] = 0.f;
    }
}

// -------- passA smem byte map (53760 B static) --------
// Stage phase:   XS f16 [c][d] @0 (8192) ; WS f16 3x @8192 (24576) ; SB @52224
// Epilogue phase: QSh f16 @0 (8192), EK f32 @17408, VS f32 @34816
__global__ void __launch_bounds__(256) passA_kernel(
    const float* __restrict__ x,
    const float* __restrict__ sk, const float* __restrict__ bk,
    const float* __restrict__ sq, const float* __restrict__ bq,
    const float* __restrict__ sv, const float* __restrict__ bv)
{
    static __shared__ __align__(16) char SM[53760];
    const u32 sb = s2u(SM);
    float* EK = (float*)(SM + 17408);
    float* VS = (float*)(SM + 34816);
    float* SB = (float*)(SM + 52224);
    const int t = threadIdx.x, lane = t & 31, w = t >> 5;
    const int grp = lane >> 2, q = lane & 3, l7 = lane & 7;
    const int b = blockIdx.x, n = b >> 12, hw = b & 4095;
    const size_t xb = (size_t)n * (64ull * PLANE) + (size_t)hw * 64;

    // ---- stage XS f16: row = token c (t&63), 2 d-chunks per thread ----
    {
        const int row = t & 63, u0 = (t >> 6) * 2;
#pragma unroll
        for (int uu = 0; uu < 2; uu++) {
            int u = u0 + uu;
            float f[8];
#pragma unroll
            for (int j = 0; j < 8; j++)
                f[j] = x[xb + (size_t)(8 * u + j) * PLANE + row];
            __half2 p[4];
#pragma unroll
            for (int j = 0; j < 4; j++) p[j] = __floats2half2_rn(f[2 * j], f[2 * j + 1]);
            *(uint4*)(SM + choff(row, u)) = *(uint4*)p;
        }
    }
    // ---- stage WqT/WkT/WvT f16 ----
    {
        const uint4* g4 = (const uint4*)g_WTh;
#pragma unroll
        for (int i = 0; i < 6; i++) {
            int idx = i * 256 + t;                 // 0..1535
            int mat = idx >> 9, rem = idx & 511;
            uint4 v = g4[idx];
            *(uint4*)(SM + 8192 + mat * 8192 + choff(rem >> 3, rem & 7)) = v;
        }
    }
    if (t < 64) {
        SB[t]       = sq[t]; SB[64  + t] = bq[t];
        SB[128 + t] = sk[t]; SB[192 + t] = bk[t];
        SB[256 + t] = sv[t]; SB[320 + t] = bv[t];
    }
    __syncthreads();

    // ---- GEMMs: warp tile = 16 rows (mtile) x 32 cols (nhalf); shared A frags ----
    const int mtile = (w & 3) * 16, nhalf = (w >> 2) * 32;
    const int arow0 = mtile + l7 + (((lane >> 3) & 1) << 3);
    const int acs = lane >> 4, bcs = (lane >> 3) & 1;
    float accQ[4][4], accK[4][4], accV[4][4];
#pragma unroll
    for (int nt = 0; nt < 4; nt++)
#pragma unroll
        for (int k = 0; k < 4; k++) { accQ[nt][k] = 0.f; accK[nt][k] = 0.f; accV[nt][k] = 0.f; }
#pragma unroll
    for (int kt = 0; kt < 4; kt++) {
        u32 a4[4];
        ldmA(sb + choff(arow0, 2 * kt + acs), a4);
#pragma unroll
        for (int nt = 0; nt < 4; nt++) {
            const u32 bo = choff(nhalf + nt * 8 + l7, 2 * kt + bcs);
            u32 b0[2], b1[2], b2[2];
            ldmB(sb + 8192 + bo, b0);
            ldmB(sb + 16384 + bo, b1);
            ldmB(sb + 24576 + bo, b2);
            mma16(accQ[nt], a4, b0);
            mma16(accK[nt], a4, b1);
            mma16(accV[nt], a4, b2);
        }
    }
    __syncthreads();      // all MMAs done; stage regions may be overwritten

    // ---- Q: quad-shuffle softmax -> QSh f16 ; K: exp -> EK ; V -> VS ----
#pragma unroll
    for (int rr = 0; rr < 2; rr++) {
        const int row = mtile + rr * 8 + grp;
#pragma unroll
        for (int nt = 0; nt < 4; nt++) {
            const int ch = nhalf + nt * 8 + 2 * q;
            {
                float y0 = lrelu(accQ[nt][rr * 2 + 0] * SB[ch]     + SB[64 + ch]);
                float y1 = lrelu(accQ[nt][rr * 2 + 1] * SB[ch + 1] + SB[64 + ch + 1]);
                float m = fmaxf(y0, y1);
                m = fmaxf(m, __shfl_xor_sync(0xffffffffu, m, 1));
                m = fmaxf(m, __shfl_xor_sync(0xffffffffu, m, 2));
                float e0 = __expf(y0 - m), e1 = __expf(y1 - m);
                float s = e0 + e1;
                s += __shfl_xor_sync(0xffffffffu, s, 1);
                s += __shfl_xor_sync(0xffffffffu, s, 2);
                float inv = 1.f / s;
                *(__half2*)(SM + qoff(row, ch)) = __floats2half2_rn(e0 * inv, e1 * inv);
            }
            {
                float e0 = __expf(lrelu(accK[nt][rr * 2 + 0] * SB[128 + ch]     + SB[192 + ch]));
                float e1 = __expf(lrelu(accK[nt][rr * 2 + 1] * SB[128 + ch + 1] + SB[192 + ch + 1]));
                *(float2*)(EK + row * 68 + ch) = make_float2(e0, e1);
            }
            {
                float v0 = lrelu(accV[nt][rr * 2 + 0] * SB[256 + ch]     + SB[320 + ch]);
                float v1 = lrelu(accV[nt][rr * 2 + 1] * SB[256 + ch + 1] + SB[320 + ch + 1]);
                *(float2*)(VS + row * 68 + ch) = make_float2(v0, v1);
            }
        }
    }
    __syncthreads();

    // ---- g_Qh write: coalesced 128B f16 rows ----
    {
        const size_t qbase = ((size_t)n * T_TOK + hw) * 64;   // halves
#pragma unroll
        for (int i = 0; i < 2; i++) {
            int idx = t + i * 256;                 // 0..511
            int row = idx >> 3, u = idx & 7;
            uint4 v = *(const uint4*)(SM + row * 128 + ((16 * u) ^ ((row & 7) << 4)));
            *(uint4*)(g_Qh + qbase + (size_t)row * PLANE + 8 * u) = v;
        }
    }

    // ---- ctx numerator/denominator (verified R1 math) ----
#pragma unroll
    for (int g = t; g < 512; g += 256) {
        int a = g >> 6, k = (g >> 3) & 7, v = g & 7;
        const float* kp = EK + a * 8 + k;
        const float* vp = VS + a * 8 + v;
        float s = 0.f;
#pragma unroll 8
        for (int c = 0; c < 64; c++) s += kp[c * 68] * vp[c * 68];
        atomicAdd(&g_ctxnum[n * 512 + g], s);
    }
    if (t < 64) {
        const float* kp = EK + t;
        float s = 0.f;
#pragma unroll 8
        for (int c = 0; c < 64; c++) s += kp[c * 68];
        atomicAdd(&g_den[n * 64 + t], s);
    }
}

// -------- passC smem byte map (36352 B static) --------
// Qs f32[64][68] @0 (17408) ; WrS f16 @17408 (8192) ; Ag f16 @25600 (8192)
// ctx @33792 (2048) ; SBc @35840 (512)
__global__ void __launch_bounds__(256) passC_kernel(
    const float* __restrict__ x,
    const float* __restrict__ sr, const float* __restrict__ br,
    float* __restrict__ out)
{
    static __shared__ __align__(16) char SM[36352];
    const u32 sb = s2u(SM);
    float* Qs   = (float*)SM;
    float* ctxs = (float*)(SM + 33792);
    float* SBc  = (float*)(SM + 35840);
    const int t = threadIdx.x, lane = t & 31, w = t >> 5;
    const int grp = lane >> 2, q = lane & 3, l7 = lane & 7;
    const int b = blockIdx.x, n = b >> 12, hw = b & 4095;
    const int h = hw >> 6, ww = hw & 63;
    const size_t qn = (size_t)n * T_TOK * 64;   // halves

    {   // stage WrS
        const uint4* g4 = (const uint4*)g_WTh + 3 * 512;
#pragma unroll
        for (int i = 0; i < 2; i++) {
            int idx = i * 256 + t;                 // 0..511
            uint4 v = g4[idx];
            *(uint4*)(SM + 17408 + choff(idx >> 3, idx & 7)) = v;
        }
    }
#pragma unroll
    for (int g = t; g < 512; g += 256)
        ctxs[g] = g_ctxnum[n * 512 + g] / g_den[n * 64 + (g >> 3)];
    if (t < 64) { SBc[t] = sr[t]; SBc[64 + t] = br[t]; }
    {   // Q gather: f16 global rows -> f32 Qs[rv][68]
#pragma unroll
        for (int i = 0; i < 2; i++) {
            int idx = t + i * 256;                 // 0..511
            int rv = idx >> 3, u = idx & 7;
            int r = rv >> 3, v = rv & 7;
            size_t R = (size_t)r * 32768 + (size_t)h * 512 + ww * 8 + v;
            uint4 q4 = *(const uint4*)(g_Qh + qn + R * 64 + 8 * u);
            const __half2* hp = (const __half2*)&q4;
            float* dst = Qs + rv * 68 + 8 * u;
            float2 f0 = __half22float2(hp[0]), f1 = __half22float2(hp[1]);
            float2 f2 = __half22float2(hp[2]), f3 = __half22float2(hp[3]);
            *(float4*)dst       = make_float4(f0.x, f0.y, f1.x, f1.y);
            *(float4*)(dst + 4) = make_float4(f2.x, f2.y, f3.x, f3.y);
        }
    }
    __syncthreads();

    // ---- agg (verified R1 math) -> Ag f16 A-tile ----
    {
        const int cg = (t & 15) << 2;
        const int eg = (t >> 4) << 2;
        const int a  = eg >> 3;
#pragma unroll
        for (int i = 0; i < 4; i++) {
            int c = cg + i;
            int k = c >> 3, rr = (c & 7) << 3;
            float4 cx0 = *(const float4*)(ctxs + (a * 8 + k) * 8);
            float4 cx1 = *(const float4*)(ctxs + (a * 8 + k) * 8 + 4);
            float av[4];
#pragma unroll
            for (int j = 0; j < 4; j++) {
                int v = (eg + j) & 7;
                const float* qp = Qs + (rr + v) * 68 + a * 8;
                float4 q0 = *(const float4*)qp;
                float4 q1 = *(const float4*)(qp + 4);
                av[j] = cx0.x * q0.x + cx0.y * q0.y + cx0.z * q0.z + cx0.w * q0.w
                      + cx1.x * q1.x + cx1.y * q1.y + cx1.z * q1.z + cx1.w * q1.w;
            }
            __half2 p0 = __floats2half2_rn(av[0], av[1]);
            __half2 p1 = __floats2half2_rn(av[2], av[3]);
            uint2 pk; pk.x = *(u32*)&p0; pk.y = *(u32*)&p1;
            *(uint2*)(SM + 25600 + choff(c, eg >> 3) + (eg & 7) * 2) = pk;
        }
    }
    __syncthreads();

    // ---- rep = agg @ Wr via MMA ----
    const int mtile = (w & 3) * 16, nhalf = (w >> 2) * 32;
    const int arow0 = mtile + l7 + (((lane >> 3) & 1) << 3);
    const int acs = lane >> 4, bcs = (lane >> 3) & 1;
    float accR[4][4];
#pragma unroll
    for (int nt = 0; nt < 4; nt++)
#pragma unroll
        for (int k = 0; k < 4; k++) accR[nt][k] = 0.f;
#pragma unroll
    for (int kt = 0; kt < 4; kt++) {
        u32 a4[4];
        ldmA(sb + 25600 + choff(arow0, 2 * kt + acs), a4);
#pragma unroll
        for (int nt = 0; nt < 4; nt++) {
            u32 b2[2];
            ldmB(sb + 17408 + choff(nhalf + nt * 8 + l7, 2 * kt + bcs), b2);
            mma16(accR[nt], a4, b2);
        }
    }

    // ---- epilogue: scale/bias/lrelu + residual ----
    {
        const size_t ob = (size_t)n * (64ull * PLANE) + (size_t)hw * 64;
#pragma unroll
        for (int rr = 0; rr < 2; rr++) {
            const int c = mtile + rr * 8 + grp;
#pragma unroll
            for (int nt = 0; nt < 4; nt++) {
#pragma unroll
                for (int j = 0; j < 2; j++) {
                    const int d = nhalf + nt * 8 + 2 * q + j;
                    float yv = lrelu(accR[nt][rr * 2 + j] * SBc[d] + SBc[64 + d]);
                    const size_t off = ob + (size_t)d * PLANE + c;
                    out[off] = yv + x[off];
                }
            }
        }
    }
}

extern "C" void kernel_launch(void* const* d_in, const int* in_sizes, int n_in,
                              void* d_out, int out_size) {
    const float* x  = (const float*)d_in[0];
    const float* Wk = (const float*)d_in[1];
    const float* sk = (const float*)d_in[2];
    const float* bk = (const float*)d_in[3];
    const float* Wq = (const float*)d_in[4];
    const float* sq = (const float*)d_in[5];
    const float* bq = (const float*)d_in[6];
    const float* Wv = (const float*)d_in[7];
    const float* sv = (const float*)d_in[8];
    const float* bv = (const float*)d_in[9];
    const float* Wr = (const float*)d_in[10];
    const float* sr = (const float*)d_in[11];
    const float* br = (const float*)d_in[12];
    float* out = (float*)d_out;

    setup_kernel<<<32, 256>>>(Wq, Wk, Wv, Wr);
    passA_kernel<<<8192, 256>>>(x, sk, bk, sq, bq, sv, bv);
    passC_kernel<<<8192, 256>>>(x, sr, br, out);
}